// round 16
// baseline (speedup 1.0000x reference)
#include <cuda_runtime.h>
#include <math.h>

#define BQ 10000
#define DD 64
#define MM 50
#define BB 64
#define TT 512
#define BT (BB*TT)              // 32768 rows
#define NW 192                  // padded weight rows for K1 (50 w | 64 e | 64 a | pad)
#define NROWS_OUT (BB*(TT-1))   // 32704
#define NCH 16                  // chunks over T
#define CHL 32                  // steps per chunk (NCH*CHL == TT)
#define MD (MM*DD)              // 3200

typedef unsigned long long u64;

// ---- packed fp32x2 helpers (Blackwell FFMA2 path) --------------------------
__device__ __forceinline__ u64 pack2(float a, float b) {
    u64 r; asm("mov.b64 %0, {%1,%2};" : "=l"(r) : "f"(a), "f"(b)); return r;
}
__device__ __forceinline__ float2 unpk2(u64 v) {
    float2 f; asm("mov.b64 {%0,%1}, %2;" : "=f"(f.x), "=f"(f.y) : "l"(v)); return f;
}
__device__ __forceinline__ u64 fma2_(u64 a, u64 b, u64 c) {
    u64 r; asm("fma.rn.f32x2 %0, %1, %2, %3;" : "=l"(r) : "l"(a), "l"(b), "l"(c)); return r;
}
__device__ __forceinline__ u64 mul2_(u64 a, u64 b) {
    u64 r; asm("mul.rn.f32x2 %0, %1, %2;" : "=l"(r) : "l"(a), "l"(b)); return r;
}

// ---- cp.async helpers ------------------------------------------------------
__device__ __forceinline__ void cp_async16(void* smem, const void* glob) {
    unsigned s = (unsigned)__cvta_generic_to_shared(smem);
    asm volatile("cp.async.cg.shared.global [%0], [%1], 16;" :: "r"(s), "l"(glob));
}
__device__ __forceinline__ void cp_commit() { asm volatile("cp.async.commit_group;"); }
__device__ __forceinline__ void cp_wait0()  { asm volatile("cp.async.wait_group 0;" ::: "memory"); }

// fast transcendentals (MUFU-based, ~1e-6 rel err, overflow-safe)
__device__ __forceinline__ float fast_sigmoid(float x) {
    return __fdividef(1.f, 1.f + __expf(-x));
}
__device__ __forceinline__ float fast_tanh(float x) {
    float t = __expf(-2.f * fabsf(x));          // in (0,1], no overflow
    float r = __fdividef(1.f - t, 1.f + t);
    return copysignf(r, x);
}

// ---------------- scratch (device globals; no allocation allowed) ----------
__device__ float g_w[BT*64];             // softmaxed w, PERMUTED: slot=(m&7)*8+(m>>3), pads 0
__device__ float g_ea[BT*128];           // interleaved (e_d0,e_d1,a_d0,a_d1) per d-pair, mask folded
__device__ float g_read[NROWS_OUT*DD];   // read vectors, row = b*(T-1)+(t-1)
__device__ float g_UC[BB*NCH*MD*2];      // interleaved (U0,U1,C0,C1) chunk aggregates
__device__ float g_mvstart[BB*NCH*MD];   // Mv state at each chunk start
__device__ float g_Wt2[NW*DD];           // combined weights for K1: row j = output col
__device__ float g_bias[NW];
__device__ float g_fWt[DD*2*DD];         // f_W transposed: [j][i], 64 x 128

// ---------------- K0: weight prep ------------------------------------------
__global__ void k0_prep(const float* __restrict__ Mk,
                        const float* __restrict__ eW,
                        const float* __restrict__ aW,
                        const float* __restrict__ eb,
                        const float* __restrict__ ab,
                        const float* __restrict__ fW) {
    int idx = blockIdx.x * blockDim.x + threadIdx.x;
    int stride = gridDim.x * blockDim.x;
    for (int p = idx; p < NW*DD; p += stride) {
        int j = p / DD, i = p % DD;
        float v = 0.f;
        if (j < 50)            v = Mk[j*DD + i];
        else if (j < 114)      v = eW[i*DD + (j-50)];
        else if (j < 178)      v = aW[i*DD + (j-114)];
        g_Wt2[p] = v;
    }
    for (int j = idx; j < NW; j += stride) {
        float bv = 0.f;
        if (j >= 50 && j < 114)        bv = eb[j-50];
        else if (j >= 114 && j < 178)  bv = ab[j-114];
        g_bias[j] = bv;
    }
    for (int p = idx; p < DD*2*DD; p += stride) {
        int j = p / (2*DD), i = p % (2*DD);
        g_fWt[p] = fW[i*DD + j];
    }
}

// tiny dummies to steer ncu's fixed profiled-launch slot (#4) onto k1_wea
__global__ void k_nop() {}

// ---------------- K1: w(+softmax,permuted) + e/a, i-split + cp.async --------
// 384 threads: j = tid>>1 output col, s = tid&1 i-half. 8 x float4 weights.
#define RB1 8
__global__ __launch_bounds__(384) void k1_wea(
    const int* __restrict__ question, const int* __restrict__ response,
    const float* __restrict__ mask,
    const float* __restrict__ k_emb,  const float* __restrict__ v_emb) {
    __shared__ __align__(16) float sx[2][RB1*128];  // double-buffered [k(64)|v(64)] x 8 rows
    __shared__ float slog[RB1][52];                 // raw w logits
    int tid = threadIdx.x;
    int j = tid >> 1, s = tid & 1;
    int lane = tid & 31, wid = tid >> 5;

    float4 wq[8];
    const float4* W4 = (const float4*)(g_Wt2 + j*DD + s*32);
#pragma unroll
    for (int u = 0; u < 8; u++) wq[u] = W4[u];
    float bias = g_bias[j];
    int qbase = ((j < 50) ? 0 : 16) + s*8;   // quad index: half of k- or v-half
    bool is_w = (j < 50), is_e = (j >= 50 && j < 114), is_a = (j >= 114 && j < 178);
    int ecol = j - 50, acol = j - 114;
    const int stride = gridDim.x*RB1;

    // prologue: stage group 0 into buffer 0 (256 float4s, tid<256)
    if (tid < 256) {
        int rr = tid >> 5, c = tid & 31;
        int r = blockIdx.x*RB1 + rr;
        int q = question[r];
        const float4* src = (c < 16)
            ? ((const float4*)k_emb) + q*16 + c
            : ((const float4*)v_emb) + (size_t)(q + BQ*response[r])*16 + (c - 16);
        cp_async16(&((float4*)sx[0])[rr*32 + c], src);
    }
    cp_commit(); cp_wait0();
    __syncthreads();

    int buf = 0;
    for (int r0b = blockIdx.x*RB1; r0b < BT; r0b += stride) {
        // issue async stage of NEXT group into other buffer
        int rnext = r0b + stride;
        if (tid < 256 && rnext < BT) {
            int rr = tid >> 5, c = tid & 31;
            int r = rnext + rr;
            int q = question[r];
            const float4* src = (c < 16)
                ? ((const float4*)k_emb) + q*16 + c
                : ((const float4*)v_emb) + (size_t)(q + BQ*response[r])*16 + (c - 16);
            cp_async16(&((float4*)sx[buf^1])[rr*32 + c], src);
        }
        cp_commit();

        // compute current buffer
        const float4* xs = (const float4*)sx[buf];
        float acc[RB1];
#pragma unroll
        for (int rr = 0; rr < RB1; rr++) acc[rr] = 0.f;
#pragma unroll
        for (int u = 0; u < 8; u++) {
            float4 w = wq[u];
#pragma unroll
            for (int rr = 0; rr < RB1; rr++) {
                float4 x = xs[rr*32 + qbase + u];
                acc[rr] = fmaf(x.x, w.x, acc[rr]);
                acc[rr] = fmaf(x.y, w.y, acc[rr]);
                acc[rr] = fmaf(x.z, w.z, acc[rr]);
                acc[rr] = fmaf(x.w, w.w, acc[rr]);
            }
        }
#pragma unroll
        for (int rr = 0; rr < RB1; rr++) {
            float a2 = acc[rr] + __shfl_down_sync(0xffffffffu, acc[rr], 1, 2);
            if (s == 0) {
                float v = a2 + bias;
                int r = r0b + rr;
                if (is_w) slog[rr][j] = v;
                else if (is_e) {
                    float mk = (mask[r] == 1.0f) ? 1.f : 0.f;
                    g_ea[(size_t)r*128 + (ecol >> 1)*4 + (ecol & 1)] = mk * fast_sigmoid(v);
                } else if (is_a) {
                    float mk = (mask[r] == 1.0f) ? 1.f : 0.f;
                    g_ea[(size_t)r*128 + (acol >> 1)*4 + 2 + (acol & 1)] = mk * fast_tanh(v);
                }
            }
        }
        __syncthreads();

        // softmax: 12 warps cycle over 8 rows; writes permuted + padded
        for (int rr = wid; rr < RB1; rr += 12) {
            size_t base = (size_t)(r0b + rr) * 64;
            float v0 = slog[rr][lane];
            float v1 = (lane < 18) ? slog[rr][lane + 32] : -1e30f;
            float mx = fmaxf(v0, v1);
#pragma unroll
            for (int o = 16; o; o >>= 1) mx = fmaxf(mx, __shfl_xor_sync(0xffffffffu, mx, o));
            float e0 = __expf(v0 - mx);
            float e1 = (lane < 18) ? __expf(v1 - mx) : 0.f;
            float sm = e0 + e1;
#pragma unroll
            for (int o = 16; o; o >>= 1) sm += __shfl_xor_sync(0xffffffffu, sm, o);
            float inv = __fdividef(1.f, sm);
            int m0 = lane, m1 = lane + 32;
            g_w[base + ((m0 & 7)*8 + (m0 >> 3))] = e0 * inv;
            g_w[base + ((m1 & 7)*8 + (m1 >> 3))] = (lane < 18) ? e1 * inv : 0.f;
        }
        cp_wait0();
        __syncthreads();
        buf ^= 1;
    }
}

// ---------------- K2a: chunk-composed coefficients (2 d-pairs/thread) -------
__global__ __launch_bounds__(128) void k2a() {
    __shared__ __align__(16) float4 s_w4[CHL*16];    // 8 KB
    __shared__ __align__(16) float4 s_ea[CHL*32];    // 16 KB
    int blk = blockIdx.x;
    int b = blk >> 4, c = blk & (NCH-1);
    int tid = threadIdx.x;
    int dq = tid >> 3, mp = tid & 7;

    const float4* wg = (const float4*)(g_w + ((size_t)b*TT + c*CHL)*64);
    const float4* eg = (const float4*)g_ea + ((size_t)b*TT + c*CHL)*32;
#pragma unroll
    for (int i = tid; i < CHL*16; i += 128) s_w4[i] = wg[i];
#pragma unroll
    for (int i = tid; i < CHL*32; i += 128) s_ea[i] = eg[i];
    __syncthreads();

    const u64 ONE2 = pack2(1.f, 1.f);
    u64 UA[7], CA[7], UB[7], CB[7];
#pragma unroll
    for (int jj = 0; jj < 7; jj++) {
        UA[jj] = ONE2; CA[jj] = 0ull;
        UB[jj] = ONE2; CB[jj] = 0ull;
    }

#pragma unroll 2
    for (int s = 0; s < CHL; s++) {
        float4 wlo = s_w4[s*16 + mp*2];
        float4 whi = s_w4[s*16 + mp*2 + 1];
        float w[7] = {wlo.x, wlo.y, wlo.z, wlo.w, whi.x, whi.y, whi.z};
        float4 eaA = s_ea[s*32 + dq];
        float4 eaB = s_ea[s*32 + dq + 16];
        u64 neA = pack2(-eaA.x, -eaA.y), aA = pack2(eaA.z, eaA.w);
        u64 neB = pack2(-eaB.x, -eaB.y), aB = pack2(eaB.z, eaB.w);
#pragma unroll
        for (int jj = 0; jj < 7; jj++) {
            u64 wp = pack2(w[jj], w[jj]);
            u64 uA = fma2_(wp, neA, ONE2);
            UA[jj] = mul2_(UA[jj], uA);
            CA[jj] = fma2_(CA[jj], uA, mul2_(wp, aA));
            u64 uB = fma2_(wp, neB, ONE2);
            UB[jj] = mul2_(UB[jj], uB);
            CB[jj] = fma2_(CB[jj], uB, mul2_(wp, aB));
        }
    }
    size_t off = (size_t)(b*NCH + c) * MD;
#pragma unroll
    for (int jj = 0; jj < 7; jj++) {
        int m = 8*jj + mp;
        if (m < MM) {
            float2 Uv = unpk2(UA[jj]), Cv = unpk2(CA[jj]);
            *(float4*)(g_UC + (off + (size_t)m*DD + dq*2)*2) =
                make_float4(Uv.x, Uv.y, Cv.x, Cv.y);
            Uv = unpk2(UB[jj]); Cv = unpk2(CB[jj]);
            *(float4*)(g_UC + (off + (size_t)m*DD + (dq+16)*2)*2) =
                make_float4(Uv.x, Uv.y, Cv.x, Cv.y);
        }
    }
}

// ---------------- K2b: compose chunk aggregates -> chunk start states -------
__global__ __launch_bounds__(256) void k2b(const float* __restrict__ Mv0) {
    int idx = blockIdx.x * blockDim.x + threadIdx.x;   // 0 .. BB*MD/2-1
    if (idx >= BB*(MD/2)) return;
    int b = idx / (MD/2), p = idx % (MD/2);
    float2 m0 = ((const float2*)Mv0)[p];
    u64 mv = pack2(m0.x, m0.y);
#pragma unroll
    for (int c = 0; c < NCH; c++) {
        size_t off = (size_t)(b*NCH + c) * MD + 2*p;
        ((float2*)g_mvstart)[off >> 1] = unpk2(mv);
        float4 uc = *(const float4*)(g_UC + off*2);    // (U0,U1,C0,C1)
        mv = fma2_(mv, pack2(uc.x, uc.y), pack2(uc.z, uc.w));
    }
}

// ---------------- K2c: replay chunks (2 d-pairs/thread), emit reads ---------
__global__ __launch_bounds__(128) void k2c() {
    __shared__ __align__(16) float4 s_w4[CHL*16];    // 8 KB
    __shared__ __align__(16) float4 s_ea[CHL*32];    // 16 KB
    int blk = blockIdx.x;
    int b = blk >> 4, c = blk & (NCH-1);
    int tid = threadIdx.x;
    int dq = tid >> 3, mp = tid & 7;

    const float4* wg = (const float4*)(g_w + ((size_t)b*TT + c*CHL)*64);
    const float4* eg = (const float4*)g_ea + ((size_t)b*TT + c*CHL)*32;
#pragma unroll
    for (int i = tid; i < CHL*16; i += 128) s_w4[i] = wg[i];
#pragma unroll
    for (int i = tid; i < CHL*32; i += 128) s_ea[i] = eg[i];

    float* rb = g_read + (size_t)b*(TT-1)*DD;
    const u64 ONE2 = pack2(1.f, 1.f);
    size_t soff = (size_t)(b*NCH + c) * MD;
    u64 mvA[7], mvB[7];
#pragma unroll
    for (int jj = 0; jj < 7; jj++) {
        int m = 8*jj + mp;
        if (m < MM) {
            float2 s0 = *(const float2*)(g_mvstart + soff + (size_t)m*DD + dq*2);
            float2 s1 = *(const float2*)(g_mvstart + soff + (size_t)m*DD + (dq+16)*2);
            mvA[jj] = pack2(s0.x, s0.y);
            mvB[jj] = pack2(s1.x, s1.y);
        } else { mvA[jj] = 0ull; mvB[jj] = 0ull; }
    }
    __syncthreads();

#pragma unroll 2
    for (int s = 0; s < CHL; s++) {
        int t = c*CHL + s;
        float4 wlo = s_w4[s*16 + mp*2];
        float4 whi = s_w4[s*16 + mp*2 + 1];
        float w[7] = {wlo.x, wlo.y, wlo.z, wlo.w, whi.x, whi.y, whi.z};
        float4 eaA = s_ea[s*32 + dq];
        float4 eaB = s_ea[s*32 + dq + 16];
        u64 neA = pack2(-eaA.x, -eaA.y), aA = pack2(eaA.z, eaA.w);
        u64 neB = pack2(-eaB.x, -eaB.y), aB = pack2(eaB.z, eaB.w);

        u64 raccA = 0ull, raccB = 0ull;
#pragma unroll
        for (int jj = 0; jj < 7; jj++) {
            u64 wp = pack2(w[jj], w[jj]);
            raccA  = fma2_(wp, mvA[jj], raccA);          // read BEFORE update
            u64 uA = fma2_(wp, neA, ONE2);
            mvA[jj] = fma2_(mvA[jj], uA, mul2_(wp, aA));
            raccB  = fma2_(wp, mvB[jj], raccB);
            u64 uB = fma2_(wp, neB, ONE2);
            mvB[jj] = fma2_(mvB[jj], uB, mul2_(wp, aB));
        }

        if (t > 0) {
            float2 ra = unpk2(raccA);
            float2 rbv = unpk2(raccB);
            float r0 = ra.x, r1 = ra.y, r2 = rbv.x, r3 = rbv.y;
#pragma unroll
            for (int o = 4; o; o >>= 1) {
                r0 += __shfl_down_sync(0xffffffffu, r0, o, 8);
                r1 += __shfl_down_sync(0xffffffffu, r1, o, 8);
                r2 += __shfl_down_sync(0xffffffffu, r2, o, 8);
                r3 += __shfl_down_sync(0xffffffffu, r3, o, 8);
            }
            if (mp == 0) {
                *(float2*)(rb + (size_t)(t-1)*DD + dq*2)        = make_float2(r0, r1);
                *(float2*)(rb + (size_t)(t-1)*DD + (dq+16)*2)   = make_float2(r2, r3);
            }
        }
    }
}

// ---------------- K3: output MLP, i-quarter split + cp.async ----------------
// 256 threads: j = tid>>2, s = tid&3. 4 x float4 weights each.
#define RB3 8
__global__ __launch_bounds__(256) void k3_out(
    const int* __restrict__ question, const float* __restrict__ k_emb,
    const float* __restrict__ f_b, const float* __restrict__ p_W,
    const float* __restrict__ p_b, float* __restrict__ out) {
    __shared__ __align__(16) float sc[2][RB3*128];  // double-buffered [read(64)|k(64)] x 8
    __shared__ float warp_ps[8][RB3];
    int tid = threadIdx.x;
    int j = tid >> 2, s = tid & 3;
    int lane = tid & 31, wid = tid >> 5;

    float4 wq[8];
    const float4* W4 = (const float4*)(g_fWt + j*128 + s*32);
#pragma unroll
    for (int u = 0; u < 8; u++) wq[u] = W4[u];
    float fb = f_b[j], pw = p_W[j];
    float pbv = p_b[0];
    int qbase = s*8;
    const int stride = gridDim.x*RB3;

    // prologue: stage group 0 (clamped addresses for OOB rows)
    {
        int rr = tid >> 5, c = tid & 31;
        int r = blockIdx.x*RB3 + rr;
        if (r >= NROWS_OUT) r = NROWS_OUT - 1;
        const float4* src;
        if (c < 16) src = ((const float4*)g_read) + (size_t)r*16 + c;
        else {
            int bb = r / (TT-1), ttt = r - bb*(TT-1);
            src = ((const float4*)k_emb) + (size_t)question[bb*TT + ttt + 1]*16 + (c - 16);
        }
        cp_async16(&((float4*)sc[0])[rr*32 + c], src);
    }
    cp_commit(); cp_wait0();
    __syncthreads();

    int buf = 0;
    for (int r0b = blockIdx.x*RB3; r0b < NROWS_OUT; r0b += stride) {
        int rnext = r0b + stride;
        if (rnext < NROWS_OUT) {
            int rr = tid >> 5, c = tid & 31;
            int r = rnext + rr;
            if (r >= NROWS_OUT) r = NROWS_OUT - 1;
            const float4* src;
            if (c < 16) src = ((const float4*)g_read) + (size_t)r*16 + c;
            else {
                int bb = r / (TT-1), ttt = r - bb*(TT-1);
                src = ((const float4*)k_emb) + (size_t)question[bb*TT + ttt + 1]*16 + (c - 16);
            }
            cp_async16(&((float4*)sc[buf^1])[rr*32 + c], src);
        }
        cp_commit();

        const float4* xs = (const float4*)sc[buf];
        float acc[RB3];
#pragma unroll
        for (int rr = 0; rr < RB3; rr++) acc[rr] = 0.f;
#pragma unroll
        for (int u = 0; u < 8; u++) {
            float4 w = wq[u];
#pragma unroll
            for (int rr = 0; rr < RB3; rr++) {
                float4 x = xs[rr*32 + qbase + u];
                acc[rr] = fmaf(x.x, w.x, acc[rr]);
                acc[rr] = fmaf(x.y, w.y, acc[rr]);
                acc[rr] = fmaf(x.z, w.z, acc[rr]);
                acc[rr] = fmaf(x.w, w.w, acc[rr]);
            }
        }
#pragma unroll
        for (int rr = 0; rr < RB3; rr++) {
            float a2 = acc[rr];
            a2 += __shfl_down_sync(0xffffffffu, a2, 2, 4);
            a2 += __shfl_down_sync(0xffffffffu, a2, 1, 4);
            float pv = (s == 0) ? fast_tanh(a2 + fb) * pw : 0.f;
#pragma unroll
            for (int o = 16; o; o >>= 1) pv += __shfl_xor_sync(0xffffffffu, pv, o);
            if (lane == 0) warp_ps[wid][rr] = pv;
        }
        __syncthreads();
        if (tid < RB3) {
            int r = r0b + tid;
            if (r < NROWS_OUT) {
                float sum = pbv;
#pragma unroll
                for (int wgi = 0; wgi < 8; wgi++) sum += warp_ps[wgi][tid];
                out[r] = sum;
            }
        }
        cp_wait0();
        __syncthreads();
        buf ^= 1;
    }
}

// ---------------- launch ----------------------------------------------------
extern "C" void kernel_launch(void* const* d_in, const int* in_sizes, int n_in,
                              void* d_out, int out_size) {
    const int*   question = (const int*)  d_in[0];
    const int*   response = (const int*)  d_in[1];
    const float* mask     = (const float*)d_in[2];
    const float* k_emb    = (const float*)d_in[3];
    const float* v_emb    = (const float*)d_in[4];
    const float* Mk       = (const float*)d_in[5];
    const float* Mv0      = (const float*)d_in[6];
    const float* e_W      = (const float*)d_in[7];
    const float* e_b      = (const float*)d_in[8];
    const float* a_W      = (const float*)d_in[9];
    const float* a_b      = (const float*)d_in[10];
    const float* f_W      = (const float*)d_in[11];
    const float* f_b      = (const float*)d_in[12];
    const float* p_W      = (const float*)d_in[13];
    const float* p_b      = (const float*)d_in[14];
    float* out = (float*)d_out;

    k0_prep<<<64, 256>>>(Mk, e_W, a_W, e_b, a_b, f_W);
    k_nop<<<1, 32>>>();      // two nops keep k1_wea in ncu's profiled slot (#4)
    k_nop<<<1, 32>>>();
    k1_wea<<<1024, 384>>>(question, response, mask, k_emb, v_emb);
    k2a<<<BB*NCH, 128>>>();
    k2b<<<(BB*(MD/2) + 255)/256, 256>>>(Mv0);
    k2c<<<BB*NCH, 128>>>();
    k3_out<<<1024, 256>>>(question, k_emb, f_b, p_W, p_b, out);
}

// round 17
// speedup vs baseline: 1.5594x; 1.5594x over previous
#include <cuda_runtime.h>
#include <math.h>

#define BQ 10000
#define DD 64
#define MM 50
#define BB 64
#define TT 512
#define BT (BB*TT)              // 32768 rows
#define NW 192                  // padded weight rows for K1 (50 w | 64 e | 64 a | pad)
#define NROWS_OUT (BB*(TT-1))   // 32704
#define NCH 16                  // chunks over T
#define CHL 32                  // steps per chunk (NCH*CHL == TT)
#define MD (MM*DD)              // 3200

typedef unsigned long long u64;

// ---- packed fp32x2 helpers (Blackwell FFMA2 path) --------------------------
__device__ __forceinline__ u64 pack2(float a, float b) {
    u64 r; asm("mov.b64 %0, {%1,%2};" : "=l"(r) : "f"(a), "f"(b)); return r;
}
__device__ __forceinline__ float2 unpk2(u64 v) {
    float2 f; asm("mov.b64 {%0,%1}, %2;" : "=f"(f.x), "=f"(f.y) : "l"(v)); return f;
}
__device__ __forceinline__ u64 fma2_(u64 a, u64 b, u64 c) {
    u64 r; asm("fma.rn.f32x2 %0, %1, %2, %3;" : "=l"(r) : "l"(a), "l"(b), "l"(c)); return r;
}
__device__ __forceinline__ u64 mul2_(u64 a, u64 b) {
    u64 r; asm("mul.rn.f32x2 %0, %1, %2;" : "=l"(r) : "l"(a), "l"(b)); return r;
}

// ---- cp.async helpers ------------------------------------------------------
__device__ __forceinline__ void cp_async16(void* smem, const void* glob) {
    unsigned s = (unsigned)__cvta_generic_to_shared(smem);
    asm volatile("cp.async.cg.shared.global [%0], [%1], 16;" :: "r"(s), "l"(glob));
}
__device__ __forceinline__ void cp_commit() { asm volatile("cp.async.commit_group;"); }
__device__ __forceinline__ void cp_wait0()  { asm volatile("cp.async.wait_group 0;" ::: "memory"); }

// fast transcendentals (MUFU-based, ~1e-6 rel err, overflow-safe)
__device__ __forceinline__ float fast_sigmoid(float x) {
    return __fdividef(1.f, 1.f + __expf(-x));
}
__device__ __forceinline__ float fast_tanh(float x) {
    float t = __expf(-2.f * fabsf(x));          // in (0,1], no overflow
    float r = __fdividef(1.f - t, 1.f + t);
    return copysignf(r, x);
}

// ---------------- scratch (device globals; no allocation allowed) ----------
__device__ float g_w[BT*64];             // softmaxed w, PERMUTED: slot=(m&7)*8+(m>>3), pads 0
__device__ float g_ea[BT*128];           // interleaved (e_d0,e_d1,a_d0,a_d1) per d-pair, mask folded
__device__ float g_read[NROWS_OUT*DD];   // read vectors, row = b*(T-1)+(t-1)
__device__ float g_UC[BB*NCH*MD*2];      // interleaved (U0,U1,C0,C1) chunk aggregates
__device__ float g_mvstart[BB*NCH*MD];   // Mv state at each chunk start
__device__ float g_Wt2[NW*DD];           // combined weights for K1: row j = output col
__device__ float g_bias[NW];
__device__ float g_fWt[DD*2*DD];         // f_W transposed: [j][i], 64 x 128

// ---------------- K0: weight prep ------------------------------------------
__global__ void k0_prep(const float* __restrict__ Mk,
                        const float* __restrict__ eW,
                        const float* __restrict__ aW,
                        const float* __restrict__ eb,
                        const float* __restrict__ ab,
                        const float* __restrict__ fW) {
    int idx = blockIdx.x * blockDim.x + threadIdx.x;
    int stride = gridDim.x * blockDim.x;
    for (int p = idx; p < NW*DD; p += stride) {
        int j = p / DD, i = p % DD;
        float v = 0.f;
        if (j < 50)            v = Mk[j*DD + i];
        else if (j < 114)      v = eW[i*DD + (j-50)];
        else if (j < 178)      v = aW[i*DD + (j-114)];
        g_Wt2[p] = v;
    }
    for (int j = idx; j < NW; j += stride) {
        float bv = 0.f;
        if (j >= 50 && j < 114)        bv = eb[j-50];
        else if (j >= 114 && j < 178)  bv = ab[j-114];
        g_bias[j] = bv;
    }
    for (int p = idx; p < DD*2*DD; p += stride) {
        int j = p / (2*DD), i = p % (2*DD);
        g_fWt[p] = fW[i*DD + j];
    }
}

// tiny dummies to steer ncu's fixed profiled-launch slot (#4) onto k1_wea
__global__ void k_nop() {}

// ---------------- K1: w(+softmax,permuted) + e/a, cp.async double-buffered --
// 192 threads, thread j = output col; 64 weights in registers (16 x float4).
// RB1=16 rows per barrier group (2 groups per block).
#define RB1 16
__global__ __launch_bounds__(192) void k1_wea(
    const int* __restrict__ question, const int* __restrict__ response,
    const float* __restrict__ mask,
    const float* __restrict__ k_emb,  const float* __restrict__ v_emb) {
    __shared__ __align__(16) float sx[2][RB1*128];  // double-buffered [k(64)|v(64)] x 16 rows
    __shared__ float slog[RB1][52];                 // raw w logits
    int tid = threadIdx.x;
    int j = tid;
    int lane = tid & 31, wid = tid >> 5;

    float4 wq[16];
    const float4* W4 = (const float4*)(g_Wt2 + j*DD);
#pragma unroll
    for (int u = 0; u < 16; u++) wq[u] = W4[u];
    float bias = g_bias[j];
    int qbase = (j < 50) ? 0 : 16;     // k-half for w, v-half for e/a
    bool is_w = (j < 50), is_e = (j >= 50 && j < 114), is_a = (j >= 114 && j < 178);
    int ecol = j - 50, acol = j - 114;
    const int stride = gridDim.x*RB1;

    // prologue: stage group 0 into buffer 0 (512 float4s over 192 threads)
    for (int i = tid; i < RB1*32; i += 192) {
        int rr = i >> 5, c = i & 31;
        int r = blockIdx.x*RB1 + rr;
        int q = question[r];
        const float4* src = (c < 16)
            ? ((const float4*)k_emb) + q*16 + c
            : ((const float4*)v_emb) + (size_t)(q + BQ*response[r])*16 + (c - 16);
        cp_async16(&((float4*)sx[0])[rr*32 + c], src);
    }
    cp_commit(); cp_wait0();
    __syncthreads();

    int buf = 0;
    for (int r0b = blockIdx.x*RB1; r0b < BT; r0b += stride) {
        // issue async stage of NEXT group into other buffer
        int rnext = r0b + stride;
        if (rnext < BT) {
            for (int i = tid; i < RB1*32; i += 192) {
                int rr = i >> 5, c = i & 31;
                int r = rnext + rr;
                int q = question[r];
                const float4* src = (c < 16)
                    ? ((const float4*)k_emb) + q*16 + c
                    : ((const float4*)v_emb) + (size_t)(q + BQ*response[r])*16 + (c - 16);
                cp_async16(&((float4*)sx[buf^1])[rr*32 + c], src);
            }
        }
        cp_commit();

        // compute current buffer
        const float4* xs = (const float4*)sx[buf];
        float acc[RB1];
#pragma unroll
        for (int rr = 0; rr < RB1; rr++) acc[rr] = 0.f;
#pragma unroll
        for (int u = 0; u < 16; u++) {
            float4 w = wq[u];
#pragma unroll
            for (int rr = 0; rr < RB1; rr++) {
                float4 x = xs[rr*32 + qbase + u];   // warp-uniform -> broadcast
                acc[rr] = fmaf(x.x, w.x, acc[rr]);
                acc[rr] = fmaf(x.y, w.y, acc[rr]);
                acc[rr] = fmaf(x.z, w.z, acc[rr]);
                acc[rr] = fmaf(x.w, w.w, acc[rr]);
            }
        }
#pragma unroll
        for (int rr = 0; rr < RB1; rr++) {
            float v = acc[rr] + bias;
            int r = r0b + rr;
            if (is_w) slog[rr][j] = v;
            else if (is_e) {
                float mk = (mask[r] == 1.0f) ? 1.f : 0.f;
                g_ea[(size_t)r*128 + (ecol >> 1)*4 + (ecol & 1)] = mk * fast_sigmoid(v);
            } else if (is_a) {
                float mk = (mask[r] == 1.0f) ? 1.f : 0.f;
                g_ea[(size_t)r*128 + (acol >> 1)*4 + 2 + (acol & 1)] = mk * fast_tanh(v);
            }
        }
        __syncthreads();

        // softmax: 6 warps cycle over 16 rows; writes permuted + padded
        for (int rr = wid; rr < RB1; rr += 6) {
            size_t base = (size_t)(r0b + rr) * 64;
            float v0 = slog[rr][lane];
            float v1 = (lane < 18) ? slog[rr][lane + 32] : -1e30f;
            float mx = fmaxf(v0, v1);
#pragma unroll
            for (int o = 16; o; o >>= 1) mx = fmaxf(mx, __shfl_xor_sync(0xffffffffu, mx, o));
            float e0 = __expf(v0 - mx);
            float e1 = (lane < 18) ? __expf(v1 - mx) : 0.f;
            float sm = e0 + e1;
#pragma unroll
            for (int o = 16; o; o >>= 1) sm += __shfl_xor_sync(0xffffffffu, sm, o);
            float inv = __fdividef(1.f, sm);
            int m0 = lane, m1 = lane + 32;
            g_w[base + ((m0 & 7)*8 + (m0 >> 3))] = e0 * inv;
            g_w[base + ((m1 & 7)*8 + (m1 >> 3))] = (lane < 18) ? e1 * inv : 0.f;
        }
        cp_wait0();
        __syncthreads();
        buf ^= 1;
    }
}

// ---------------- K2a: chunk-composed coefficients (2 d-pairs/thread) -------
__global__ __launch_bounds__(128) void k2a() {
    __shared__ __align__(16) float4 s_w4[CHL*16];    // 8 KB
    __shared__ __align__(16) float4 s_ea[CHL*32];    // 16 KB
    int blk = blockIdx.x;
    int b = blk >> 4, c = blk & (NCH-1);
    int tid = threadIdx.x;
    int dq = tid >> 3, mp = tid & 7;

    const float4* wg = (const float4*)(g_w + ((size_t)b*TT + c*CHL)*64);
    const float4* eg = (const float4*)g_ea + ((size_t)b*TT + c*CHL)*32;
#pragma unroll
    for (int i = tid; i < CHL*16; i += 128) s_w4[i] = wg[i];
#pragma unroll
    for (int i = tid; i < CHL*32; i += 128) s_ea[i] = eg[i];
    __syncthreads();

    const u64 ONE2 = pack2(1.f, 1.f);
    u64 UA[7], CA[7], UB[7], CB[7];
#pragma unroll
    for (int jj = 0; jj < 7; jj++) {
        UA[jj] = ONE2; CA[jj] = 0ull;
        UB[jj] = ONE2; CB[jj] = 0ull;
    }

#pragma unroll 2
    for (int s = 0; s < CHL; s++) {
        float4 wlo = s_w4[s*16 + mp*2];
        float4 whi = s_w4[s*16 + mp*2 + 1];
        float w[7] = {wlo.x, wlo.y, wlo.z, wlo.w, whi.x, whi.y, whi.z};
        float4 eaA = s_ea[s*32 + dq];
        float4 eaB = s_ea[s*32 + dq + 16];
        u64 neA = pack2(-eaA.x, -eaA.y), aA = pack2(eaA.z, eaA.w);
        u64 neB = pack2(-eaB.x, -eaB.y), aB = pack2(eaB.z, eaB.w);
#pragma unroll
        for (int jj = 0; jj < 7; jj++) {
            u64 wp = pack2(w[jj], w[jj]);
            u64 uA = fma2_(wp, neA, ONE2);
            UA[jj] = mul2_(UA[jj], uA);
            CA[jj] = fma2_(CA[jj], uA, mul2_(wp, aA));
            u64 uB = fma2_(wp, neB, ONE2);
            UB[jj] = mul2_(UB[jj], uB);
            CB[jj] = fma2_(CB[jj], uB, mul2_(wp, aB));
        }
    }
    size_t off = (size_t)(b*NCH + c) * MD;
#pragma unroll
    for (int jj = 0; jj < 7; jj++) {
        int m = 8*jj + mp;
        if (m < MM) {
            float2 Uv = unpk2(UA[jj]), Cv = unpk2(CA[jj]);
            *(float4*)(g_UC + (off + (size_t)m*DD + dq*2)*2) =
                make_float4(Uv.x, Uv.y, Cv.x, Cv.y);
            Uv = unpk2(UB[jj]); Cv = unpk2(CB[jj]);
            *(float4*)(g_UC + (off + (size_t)m*DD + (dq+16)*2)*2) =
                make_float4(Uv.x, Uv.y, Cv.x, Cv.y);
        }
    }
}

// ---------------- K2b: compose chunk aggregates -> chunk start states -------
__global__ __launch_bounds__(256) void k2b(const float* __restrict__ Mv0) {
    int idx = blockIdx.x * blockDim.x + threadIdx.x;   // 0 .. BB*MD/2-1
    if (idx >= BB*(MD/2)) return;
    int b = idx / (MD/2), p = idx % (MD/2);
    float2 m0 = ((const float2*)Mv0)[p];
    u64 mv = pack2(m0.x, m0.y);
#pragma unroll
    for (int c = 0; c < NCH; c++) {
        size_t off = (size_t)(b*NCH + c) * MD + 2*p;
        ((float2*)g_mvstart)[off >> 1] = unpk2(mv);
        float4 uc = *(const float4*)(g_UC + off*2);    // (U0,U1,C0,C1)
        mv = fma2_(mv, pack2(uc.x, uc.y), pack2(uc.z, uc.w));
    }
}

// ---------------- K2c: replay chunks (2 d-pairs/thread), emit reads ---------
__global__ __launch_bounds__(128) void k2c() {
    __shared__ __align__(16) float4 s_w4[CHL*16];    // 8 KB
    __shared__ __align__(16) float4 s_ea[CHL*32];    // 16 KB
    int blk = blockIdx.x;
    int b = blk >> 4, c = blk & (NCH-1);
    int tid = threadIdx.x;
    int dq = tid >> 3, mp = tid & 7;

    const float4* wg = (const float4*)(g_w + ((size_t)b*TT + c*CHL)*64);
    const float4* eg = (const float4*)g_ea + ((size_t)b*TT + c*CHL)*32;
#pragma unroll
    for (int i = tid; i < CHL*16; i += 128) s_w4[i] = wg[i];
#pragma unroll
    for (int i = tid; i < CHL*32; i += 128) s_ea[i] = eg[i];

    float* rb = g_read + (size_t)b*(TT-1)*DD;
    const u64 ONE2 = pack2(1.f, 1.f);
    size_t soff = (size_t)(b*NCH + c) * MD;
    u64 mvA[7], mvB[7];
#pragma unroll
    for (int jj = 0; jj < 7; jj++) {
        int m = 8*jj + mp;
        if (m < MM) {
            float2 s0 = *(const float2*)(g_mvstart + soff + (size_t)m*DD + dq*2);
            float2 s1 = *(const float2*)(g_mvstart + soff + (size_t)m*DD + (dq+16)*2);
            mvA[jj] = pack2(s0.x, s0.y);
            mvB[jj] = pack2(s1.x, s1.y);
        } else { mvA[jj] = 0ull; mvB[jj] = 0ull; }
    }
    __syncthreads();

#pragma unroll 2
    for (int s = 0; s < CHL; s++) {
        int t = c*CHL + s;
        float4 wlo = s_w4[s*16 + mp*2];
        float4 whi = s_w4[s*16 + mp*2 + 1];
        float w[7] = {wlo.x, wlo.y, wlo.z, wlo.w, whi.x, whi.y, whi.z};
        float4 eaA = s_ea[s*32 + dq];
        float4 eaB = s_ea[s*32 + dq + 16];
        u64 neA = pack2(-eaA.x, -eaA.y), aA = pack2(eaA.z, eaA.w);
        u64 neB = pack2(-eaB.x, -eaB.y), aB = pack2(eaB.z, eaB.w);

        u64 raccA = 0ull, raccB = 0ull;
#pragma unroll
        for (int jj = 0; jj < 7; jj++) {
            u64 wp = pack2(w[jj], w[jj]);
            raccA  = fma2_(wp, mvA[jj], raccA);          // read BEFORE update
            u64 uA = fma2_(wp, neA, ONE2);
            mvA[jj] = fma2_(mvA[jj], uA, mul2_(wp, aA));
            raccB  = fma2_(wp, mvB[jj], raccB);
            u64 uB = fma2_(wp, neB, ONE2);
            mvB[jj] = fma2_(mvB[jj], uB, mul2_(wp, aB));
        }

        if (t > 0) {
            float2 ra = unpk2(raccA);
            float2 rbv = unpk2(raccB);
            float r0 = ra.x, r1 = ra.y, r2 = rbv.x, r3 = rbv.y;
#pragma unroll
            for (int o = 4; o; o >>= 1) {
                r0 += __shfl_down_sync(0xffffffffu, r0, o, 8);
                r1 += __shfl_down_sync(0xffffffffu, r1, o, 8);
                r2 += __shfl_down_sync(0xffffffffu, r2, o, 8);
                r3 += __shfl_down_sync(0xffffffffu, r3, o, 8);
            }
            if (mp == 0) {
                *(float2*)(rb + (size_t)(t-1)*DD + dq*2)        = make_float2(r0, r1);
                *(float2*)(rb + (size_t)(t-1)*DD + (dq+16)*2)   = make_float2(r2, r3);
            }
        }
    }
}

// ---------------- K3: output MLP, cp.async double-buffered ------------------
// 128 threads: j = tid>>1, s = tid&1 (i-half). 64 weights in registers. RB3=16.
#define RB3 16
__global__ __launch_bounds__(128) void k3_out(
    const int* __restrict__ question, const float* __restrict__ k_emb,
    const float* __restrict__ f_b, const float* __restrict__ p_W,
    const float* __restrict__ p_b, float* __restrict__ out) {
    __shared__ __align__(16) float sc[2][RB3*128];  // double-buffered [read(64)|k(64)] x 16
    __shared__ float warp_ps[4][RB3];
    int tid = threadIdx.x;
    int j = tid >> 1, s = tid & 1;
    int lane = tid & 31, wid = tid >> 5;

    float4 wq[16];
    const float4* W4 = (const float4*)(g_fWt + j*128 + s*64);
#pragma unroll
    for (int u = 0; u < 16; u++) wq[u] = W4[u];
    float fb = f_b[j], pw = p_W[j];
    float pbv = p_b[0];
    int qbase = s*16;
    const int stride = gridDim.x*RB3;

    // prologue: stage group 0 (clamped addresses for OOB rows)
    for (int i = tid; i < RB3*32; i += 128) {
        int rr = i >> 5, c = i & 31;
        int r = blockIdx.x*RB3 + rr;
        if (r >= NROWS_OUT) r = NROWS_OUT - 1;
        const float4* src;
        if (c < 16) src = ((const float4*)g_read) + (size_t)r*16 + c;
        else {
            int bb = r / (TT-1), ttt = r - bb*(TT-1);
            src = ((const float4*)k_emb) + (size_t)question[bb*TT + ttt + 1]*16 + (c - 16);
        }
        cp_async16(&((float4*)sc[0])[rr*32 + c], src);
    }
    cp_commit(); cp_wait0();
    __syncthreads();

    int buf = 0;
    for (int r0b = blockIdx.x*RB3; r0b < NROWS_OUT; r0b += stride) {
        int rnext = r0b + stride;
        if (rnext < NROWS_OUT) {
            for (int i = tid; i < RB3*32; i += 128) {
                int rr = i >> 5, c = i & 31;
                int r = rnext + rr;
                if (r >= NROWS_OUT) r = NROWS_OUT - 1;
                const float4* src;
                if (c < 16) src = ((const float4*)g_read) + (size_t)r*16 + c;
                else {
                    int bb = r / (TT-1), ttt = r - bb*(TT-1);
                    src = ((const float4*)k_emb) + (size_t)question[bb*TT + ttt + 1]*16 + (c - 16);
                }
                cp_async16(&((float4*)sc[buf^1])[rr*32 + c], src);
            }
        }
        cp_commit();

        const float4* xs = (const float4*)sc[buf];
        float acc[RB3];
#pragma unroll
        for (int rr = 0; rr < RB3; rr++) acc[rr] = 0.f;
#pragma unroll
        for (int u = 0; u < 16; u++) {
            float4 w = wq[u];
#pragma unroll
            for (int rr = 0; rr < RB3; rr++) {
                float4 x = xs[rr*32 + qbase + u];
                acc[rr] = fmaf(x.x, w.x, acc[rr]);
                acc[rr] = fmaf(x.y, w.y, acc[rr]);
                acc[rr] = fmaf(x.z, w.z, acc[rr]);
                acc[rr] = fmaf(x.w, w.w, acc[rr]);
            }
        }
#pragma unroll
        for (int rr = 0; rr < RB3; rr++) {
            float a2 = acc[rr] + __shfl_down_sync(0xffffffffu, acc[rr], 1, 2);
            float pv = (s == 0) ? fast_tanh(a2 + fb) * pw : 0.f;
#pragma unroll
            for (int o = 16; o; o >>= 1) pv += __shfl_xor_sync(0xffffffffu, pv, o);
            if (lane == 0) warp_ps[wid][rr] = pv;
        }
        __syncthreads();
        if (tid < RB3) {
            int r = r0b + tid;
            if (r < NROWS_OUT) {
                float sum = pbv;
#pragma unroll
                for (int wgi = 0; wgi < 4; wgi++) sum += warp_ps[wgi][tid];
                out[r] = sum;
            }
        }
        cp_wait0();
        __syncthreads();
        buf ^= 1;
    }
}

// ---------------- launch ----------------------------------------------------
extern "C" void kernel_launch(void* const* d_in, const int* in_sizes, int n_in,
                              void* d_out, int out_size) {
    const int*   question = (const int*)  d_in[0];
    const int*   response = (const int*)  d_in[1];
    const float* mask     = (const float*)d_in[2];
    const float* k_emb    = (const float*)d_in[3];
    const float* v_emb    = (const float*)d_in[4];
    const float* Mk       = (const float*)d_in[5];
    const float* Mv0      = (const float*)d_in[6];
    const float* e_W      = (const float*)d_in[7];
    const float* e_b      = (const float*)d_in[8];
    const float* a_W      = (const float*)d_in[9];
    const float* a_b      = (const float*)d_in[10];
    const float* f_W      = (const float*)d_in[11];
    const float* f_b      = (const float*)d_in[12];
    const float* p_W      = (const float*)d_in[13];
    const float* p_b      = (const float*)d_in[14];
    float* out = (float*)d_out;

    k0_prep<<<64, 256>>>(Mk, e_W, a_W, e_b, a_b, f_W);
    k_nop<<<1, 32>>>();      // two nops keep k1_wea in ncu's profiled slot (#4)
    k_nop<<<1, 32>>>();
    k1_wea<<<1024, 192>>>(question, response, mask, k_emb, v_emb);
    k2a<<<BB*NCH, 128>>>();
    k2b<<<(BB*(MD/2) + 255)/256, 256>>>(Mv0);
    k2c<<<BB*NCH, 128>>>();
    k3_out<<<1024, 128>>>(question, k_emb, f_b, p_W, p_b, out);
}